// round 1
// baseline (speedup 1.0000x reference)
#include <cuda_runtime.h>

#define Bc 2
#define Tc 2048
#define Cc 512
#define Hc 8
#define HDc 64
#define TOPKc 64
#define BHc (Bc*Hc)
#define Mr (Bc*Tc)
#define QT 4

// Scratch (allocations are forbidden; device globals are the sanctioned path)
__device__ float g_Qh[BHc*Tc*HDc];
__device__ float g_Kh[BHc*Tc*HDc];
__device__ float g_Vh[BHc*Tc*HDc];
__device__ float g_Y [Bc*Tc*Cc];

// Order-preserving float<->uint transforms (strictly monotonic, injective)
__device__ __forceinline__ unsigned f2u(float f) {
    unsigned b = __float_as_uint(f);
    return b ^ ((unsigned)((int)b >> 31) | 0x80000000u);
}
__device__ __forceinline__ float u2f(unsigned u) {
    unsigned b = (u & 0x80000000u) ? (u ^ 0x80000000u) : ~u;
    return __uint_as_float(b);
}

// ---------------------------------------------------------------------------
// SGEMM: out(M=4096, N=512) = A(4096x512) @ W(512x512) + bias
// BM=128, BN=64, BK=8, 128 threads, 8x8 per-thread microtile.
// headMajor=1: scatter into (b, h, t, d) layout for Q/K/V heads.
// ---------------------------------------------------------------------------
__global__ void __launch_bounds__(128)
sgemm_kernel(const float* __restrict__ A, const float* __restrict__ W,
             const float* __restrict__ bias, float* __restrict__ out,
             int headMajor)
{
    const int K = Cc, N = Cc;
    __shared__ float As[8][128];
    __shared__ float Bs[8][64];

    int tid = threadIdx.x;
    int bm = blockIdx.y * 128;
    int bn = blockIdx.x * 64;
    int ty = tid >> 3;     // 0..15 -> rows (x8)
    int tx = tid & 7;      // 0..7  -> cols (x8)

    float acc[8][8];
    #pragma unroll
    for (int i = 0; i < 8; i++)
        #pragma unroll
        for (int j = 0; j < 8; j++) acc[i][j] = 0.f;

    const float4* aP = reinterpret_cast<const float4*>(A + (size_t)(bm + tid) * K);
    int brow = tid >> 4;           // 0..7
    int bcol = (tid & 15) << 2;    // 0..60

    for (int kb = 0; kb < K; kb += 8) {
        float4 a0 = aP[(kb >> 2)];
        float4 a1 = aP[(kb >> 2) + 1];
        float4 bv = *reinterpret_cast<const float4*>(W + (size_t)(kb + brow) * N + bn + bcol);
        __syncthreads();
        As[0][tid] = a0.x; As[1][tid] = a0.y; As[2][tid] = a0.z; As[3][tid] = a0.w;
        As[4][tid] = a1.x; As[5][tid] = a1.y; As[6][tid] = a1.z; As[7][tid] = a1.w;
        *reinterpret_cast<float4*>(&Bs[brow][bcol]) = bv;
        __syncthreads();
        #pragma unroll
        for (int k = 0; k < 8; k++) {
            float a[8], b[8];
            #pragma unroll
            for (int i = 0; i < 8; i++) a[i] = As[k][ty * 8 + i];
            #pragma unroll
            for (int j = 0; j < 8; j++) b[j] = Bs[k][tx * 8 + j];
            #pragma unroll
            for (int i = 0; i < 8; i++)
                #pragma unroll
                for (int j = 0; j < 8; j++) acc[i][j] += a[i] * b[j];
        }
    }

    #pragma unroll
    for (int i = 0; i < 8; i++) {
        int m = bm + ty * 8 + i;
        int b = m >> 11;             // / Tc
        int t = m & (Tc - 1);
        #pragma unroll
        for (int j = 0; j < 8; j++) {
            int n = bn + tx * 8 + j;
            float v = acc[i][j] + bias[n];
            if (headMajor) {
                int h = n >> 6, d = n & 63;
                out[((size_t)((b * Hc + h) * Tc + t) << 6) + d] = v;
            } else {
                out[(size_t)m * N + n] = v;
            }
        }
    }
}

// ---------------------------------------------------------------------------
// V normalization: one warp per (b,h,t) row of 64 elements.
// vh = vh / max(||vh||, 1e-12)
// ---------------------------------------------------------------------------
__global__ void vnorm_kernel(float* __restrict__ V)
{
    int row = blockIdx.x * 8 + (threadIdx.x >> 5);
    int lane = threadIdx.x & 31;
    float2* vr = reinterpret_cast<float2*>(V + (size_t)row * HDc);
    float2 v = vr[lane];
    float ss = v.x * v.x + v.y * v.y;
    #pragma unroll
    for (int off = 16; off; off >>= 1) ss += __shfl_xor_sync(0xffffffffu, ss, off);
    float scale = 1.0f / fmaxf(sqrtf(ss), 1e-12f);
    v.x *= scale; v.y *= scale;
    vr[lane] = v;
}

// ---------------------------------------------------------------------------
// Attention: per block QT=4 consecutive query rows of one (b,h).
// 512 threads, 128 per row. Phases: scores -> exact rank-64 radix select ->
// deterministic compaction -> softmax over survivors -> sparse PV.
// ---------------------------------------------------------------------------
struct AttnSmem {
    float          qs[QT][HDc];
    unsigned       su[QT][Tc];        // scores as order-preserving uints; later softmax probs
    float          ybuf[QT][128];
    unsigned       s_red[QT][4];
    float          s_fred[QT][4];
    int            s_wsum[QT][4];
    unsigned short sidx[QT][Tc];      // survivor key indices
};

__global__ void __launch_bounds__(512)
attn_kernel(const float* __restrict__ Q, const float* __restrict__ K,
            const float* __restrict__ V, float* __restrict__ Y)
{
    extern __shared__ unsigned char smem_raw[];
    AttnSmem* S = reinterpret_cast<AttnSmem*>(smem_raw);

    int tid   = threadIdx.x;
    int row   = tid >> 7;          // 0..3 (query row within block)
    int rt    = tid & 127;         // thread within row
    int lane  = tid & 31;
    int rwarp = (tid >> 5) & 3;    // warp within row

    int bh = blockIdx.y;
    int qi = blockIdx.x * QT + row;
    int n  = qi + 1;               // causal: keys 0..qi valid

    const float* Qr = Q + (size_t)(bh * Tc + qi) * HDc;
    const float* Kb = K + (size_t)bh * Tc * HDc;
    const float* Vb = V + (size_t)bh * Tc * HDc;

    if (rt < HDc) S->qs[row][rt] = Qr[rt];
    __syncthreads();

    // ---- Phase B: scores s[k] = (q . k_k) * 0.125, stored as ordered uints
    const float4* q4 = reinterpret_cast<const float4*>(S->qs[row]);
    for (int k = rt; k < n; k += 128) {
        const float4* k4 = reinterpret_cast<const float4*>(Kb + (size_t)k * HDc);
        float acc = 0.f;
        #pragma unroll
        for (int i = 0; i < 16; i++) {
            float4 kv = k4[i], qv = q4[i];
            acc += kv.x * qv.x + kv.y * qv.y + kv.z * qv.z + kv.w * qv.w;
        }
        S->su[row][k] = f2u(acc * 0.125f);
    }
    __syncthreads();

    // ---- Phase C: exact 64th-largest via 32-pass MSB binary search.
    // Always executed by all threads (uniform __syncthreads); result ignored
    // for n <= TOPK rows.
    unsigned prefix = 0; int need = TOPKc;
    #pragma unroll 1
    for (int bit = 31; bit >= 0; --bit) {
        unsigned test = prefix | (1u << bit);
        unsigned msk  = ~((1u << bit) - 1u);
        int cnt = 0;
        for (int k = rt; k < n; k += 128)
            cnt += ((S->su[row][k] & msk) == test) ? 1 : 0;
        #pragma unroll
        for (int off = 16; off; off >>= 1) cnt += __shfl_xor_sync(0xffffffffu, cnt, off);
        if (lane == 0) S->s_red[row][rwarp] = (unsigned)cnt;
        __syncthreads();
        cnt = (int)(S->s_red[row][0] + S->s_red[row][1] + S->s_red[row][2] + S->s_red[row][3]);
        __syncthreads();
        if (cnt >= need) prefix = test; else need -= cnt;
    }
    unsigned thrU = (n > TOPKc) ? prefix : 0u;   // keep all when row shorter than TOPK

    // ---- Phase D: deterministic compaction (count + scan + ordered write), plus max
    int cloc = 0; unsigned umax = 0u;
    for (int k = rt; k < n; k += 128) {
        unsigned u = S->su[row][k];
        umax = max(umax, u);
        cloc += (u >= thrU) ? 1 : 0;
    }
    int inc = cloc;
    #pragma unroll
    for (int off = 1; off < 32; off <<= 1) {
        int v = __shfl_up_sync(0xffffffffu, inc, off);
        if (lane >= off) inc += v;
    }
    if (lane == 31) S->s_wsum[row][rwarp] = inc;
    #pragma unroll
    for (int off = 16; off; off >>= 1) umax = max(umax, __shfl_xor_sync(0xffffffffu, umax, off));
    if (lane == 0) S->s_red[row][rwarp] = umax;
    __syncthreads();
    int wbase = 0;
    #pragma unroll
    for (int w = 0; w < 4; w++) if (w < rwarp) wbase += S->s_wsum[row][w];
    int m = S->s_wsum[row][0] + S->s_wsum[row][1] + S->s_wsum[row][2] + S->s_wsum[row][3];
    umax = max(max(S->s_red[row][0], S->s_red[row][1]),
               max(S->s_red[row][2], S->s_red[row][3]));
    int pos = wbase + inc - cloc;  // exclusive prefix for this thread
    for (int k = rt; k < n; k += 128) {
        if (S->su[row][k] >= thrU) S->sidx[row][pos++] = (unsigned short)k;
    }
    __syncthreads();

    // ---- Phase F: softmax numerator + sum over survivors (probs overwrite su in place)
    float maxf = u2f(umax);
    float lsum = 0.f;
    for (int j = rt; j < m; j += 128) {
        int k = S->sidx[row][j];
        float p = __expf(u2f(S->su[row][k]) - maxf);
        S->su[row][k] = __float_as_uint(p);
        lsum += p;
    }
    #pragma unroll
    for (int off = 16; off; off >>= 1) lsum += __shfl_xor_sync(0xffffffffu, lsum, off);
    if (lane == 0) S->s_fred[row][rwarp] = lsum;
    __syncthreads();
    float sum = S->s_fred[row][0] + S->s_fred[row][1] + S->s_fred[row][2] + S->s_fred[row][3];
    float rinv = 1.0f / sum;

    // ---- Phase G: sparse PV over ~64 survivors. threads = (d, part)
    int d = rt & 63, part = rt >> 6;
    float acc = 0.f;
    for (int j = part; j < m; j += 2) {
        int k = S->sidx[row][j];
        acc += __uint_as_float(S->su[row][k]) * Vb[(size_t)k * HDc + d];
    }
    S->ybuf[row][rt] = acc;
    __syncthreads();
    if (rt < 64) {
        float y = (S->ybuf[row][rt] + S->ybuf[row][rt + 64]) * rinv;
        int b = bh >> 3, h = bh & 7;   // bh = b*H + h
        Y[(size_t)(b * Tc + qi) * Cc + h * HDc + rt] = y;
    }
}

// ---------------------------------------------------------------------------
extern "C" void kernel_launch(void* const* d_in, const int* in_sizes, int n_in,
                              void* d_out, int out_size)
{
    // metadata order: q, tgt_mask, Wq, bq, Wk, bk, Wv, bv, Wp, bp
    const float* q  = (const float*)d_in[0];
    // d_in[1] = tgt_mask (causal; structure known, not read)
    const float* Wq = (const float*)d_in[2];
    const float* bq = (const float*)d_in[3];
    const float* Wk = (const float*)d_in[4];
    const float* bk = (const float*)d_in[5];
    const float* Wv = (const float*)d_in[6];
    const float* bv = (const float*)d_in[7];
    const float* Wp = (const float*)d_in[8];
    const float* bp = (const float*)d_in[9];

    float *Qh, *Kh, *Vh, *Yb;
    cudaGetSymbolAddress((void**)&Qh, g_Qh);
    cudaGetSymbolAddress((void**)&Kh, g_Kh);
    cudaGetSymbolAddress((void**)&Vh, g_Vh);
    cudaGetSymbolAddress((void**)&Yb, g_Y);

    cudaFuncSetAttribute(attn_kernel, cudaFuncAttributeMaxDynamicSharedMemorySize,
                         (int)sizeof(AttnSmem));

    dim3 gg(Cc / 64, Mr / 128);   // (8, 32)
    sgemm_kernel<<<gg, 128>>>(q, Wq, bq, Qh, 1);
    sgemm_kernel<<<gg, 128>>>(q, Wk, bk, Kh, 1);
    sgemm_kernel<<<gg, 128>>>(q, Wv, bv, Vh, 1);
    vnorm_kernel<<<(BHc * Tc) / 8, 256>>>(Vh);
    attn_kernel<<<dim3(Tc / QT, BHc), 512, sizeof(AttnSmem)>>>(Qh, Kh, Vh, Yb);
    sgemm_kernel<<<gg, 128>>>(Yb, Wp, bp, (float*)d_out, 0);
}